// round 14
// baseline (speedup 1.0000x reference)
#include <cuda_runtime.h>
#include <cuda_fp16.h>
#include <cstdint>

#define NODES 100000
#define EDGES 1600000
#define TILES 782            // 782 * 128 = 100096
#define NPAD  100096
#define CHUNK 1024
#define NCHUNK 98

// ---------------- scratch (device globals; no allocation) ----------------
__device__ int   d_deg[NODES];
__device__ int   d_cursor[NODES];       // initialized to row start by k_scan
__device__ int   d_row[NODES + 1];      // FINAL absolute CSR offsets
__device__ int   d_csr[EDGES];
__device__ int   d_tot[NCHUNK];
__device__ unsigned d_bar1;
__device__ int   d_t1, d_t2;            // GEMM tile work-stealing counters
__device__ uint2 d_xh[NODES * 32];      // x in fp16 (128 halfs/row)
__device__ uint2 d_mean1h[NPAD * 32];   // mean-aggregated x, fp16
__device__ uint32_t d_h1h[NPAD * 64];   // layer1 output, fp16
__device__ uint32_t d_plh[NPAD * 32];   // h1 @ W2l^T, fp16
__device__ uint32_t d_prh[NPAD * 32];   // h1 @ W2r^T, fp16
__device__ uint32_t d_wt1p[16384];      // [W1l;W1r] pre-packed fragment layout
__device__ uint32_t d_wt2p[8192];       // [W2l|W2r] pre-packed

// ---------------- helpers ----------------
__device__ __forceinline__ uint32_t packh2(float a, float b) {
    half2 h = __floats2half2_rn(a, b);
    return *(uint32_t*)&h;
}
__device__ __forceinline__ float2 unph2(uint32_t u) {
    return __half22float2(*(half2*)&u);
}
__device__ __forceinline__ uint32_t hadd2u(uint32_t a, uint32_t b) {
    half2 r = __hadd2(*(half2*)&a, *(half2*)&b);
    return *(uint32_t*)&r;
}

__device__ __forceinline__ void mmah(float* d, const uint32_t* a, uint2 b) {
    asm volatile(
        "mma.sync.aligned.m16n8k16.row.col.f32.f16.f16.f32 "
        "{%0,%1,%2,%3}, {%4,%5,%6,%7}, {%8,%9}, {%0,%1,%2,%3};\n"
        : "+f"(d[0]), "+f"(d[1]), "+f"(d[2]), "+f"(d[3])
        : "r"(a[0]), "r"(a[1]), "r"(a[2]), "r"(a[3]), "r"(b.x), "r"(b.y));
}

__device__ __forceinline__ float wt1_at(const float* W1l, const float* W1r, int n, int k) {
    return (k < 128) ? W1l[n * 128 + k] : W1r[n * 128 + (k - 128)];
}
__device__ __forceinline__ float wt2_at(const float* W2l, const float* W2r, int n, int k) {
    return (n < 64) ? W2l[n * 128 + k] : W2r[(n - 64) * 128 + k];
}

// ---------------- init: zero deg + x->fp16 + weight pre-pack ----------------
__global__ void k_init(const float* __restrict__ x,
                       const float* __restrict__ W1l, const float* __restrict__ W1r,
                       const float* __restrict__ W2l, const float* __restrict__ W2r) {
    int i = blockIdx.x * blockDim.x + threadIdx.x;
    if (i == 0) { d_bar1 = 0; d_t1 = 0; d_t2 = 0; }
    if (i < NODES) d_deg[i] = 0;
    if (i < NODES * 32) {
        float4 v = ((const float4*)x)[i];
        d_xh[i] = make_uint2(packh2(v.x, v.y), packh2(v.z, v.w));
    }
    if (i < 16384) {
        int w = i & 7, n = (i >> 3) & 127, ks = i >> 10;
        int p = w >> 1;
        int kb = (w & 1) ? (2 * p + 8) : (2 * p);
        int k = ks * 16 + kb;
        d_wt1p[i] = packh2(wt1_at(W1l, W1r, n, k), wt1_at(W1l, W1r, n, k + 1));
    }
    if (i < 8192) {
        int w = i & 7, n = (i >> 3) & 127, ks = i >> 10;
        int p = w >> 1;
        int kb = (w & 1) ? (2 * p + 8) : (2 * p);
        int k = ks * 16 + kb;
        d_wt2p[i] = packh2(wt2_at(W2l, W2r, n, k), wt2_at(W2l, W2r, n, k + 1));
    }
}

// ---------------- hist ----------------
__global__ void k_hist(const int* __restrict__ dst) {
    int i = blockIdx.x * blockDim.x + threadIdx.x;
    if (i < EDGES) atomicAdd(&d_deg[dst[i]], 1);
}

// ---------------- merged scan (98 co-resident blocks, spin barrier) ----------------
__global__ void __launch_bounds__(1024) k_scan() {
    __shared__ int ws[32];
    __shared__ int tot_s[128];
    __shared__ int s_off;
    int b = blockIdx.x;
    int i = b * CHUNK + threadIdx.x;
    int lane = threadIdx.x & 31, wid = threadIdx.x >> 5;

    int v = (i < NODES) ? d_deg[i] : 0;
    int xv = v;
    #pragma unroll
    for (int o = 1; o < 32; o <<= 1) {
        int y = __shfl_up_sync(0xffffffffu, xv, o);
        if (lane >= o) xv += y;
    }
    if (lane == 31) ws[wid] = xv;
    __syncthreads();
    if (wid == 0) {
        int s = ws[lane];
        #pragma unroll
        for (int o = 1; o < 32; o <<= 1) {
            int y = __shfl_up_sync(0xffffffffu, s, o);
            if (lane >= o) s += y;
        }
        ws[lane] = s;
    }
    __syncthreads();
    int incl = xv + (wid > 0 ? ws[wid - 1] : 0);
    int excl = incl - v;
    if (threadIdx.x == CHUNK - 1) d_tot[b] = incl;

    __threadfence();
    __syncthreads();
    if (threadIdx.x == 0) {
        atomicAdd(&d_bar1, 1u);
        while (atomicAdd(&d_bar1, 0u) < (unsigned)gridDim.x) {}
    }
    __syncthreads();

    if (threadIdx.x < 128) tot_s[threadIdx.x] = (threadIdx.x < NCHUNK) ? d_tot[threadIdx.x] : 0;
    __syncthreads();
    if (threadIdx.x == 0) {
        int s = 0;
        for (int c = 0; c < b; c++) s += tot_s[c];
        s_off = s;
    }
    __syncthreads();
    int abs_off = excl + s_off;
    if (i <= NODES) d_row[i] = abs_off;
    if (i < NODES)  d_cursor[i] = abs_off;
}

// ---------------- scatter: 2 random accesses per edge ----------------
__global__ void k_scatter(const int* __restrict__ src, const int* __restrict__ dst) {
    int i = blockIdx.x * blockDim.x + threadIdx.x;
    if (i < EDGES) {
        int o = atomicAdd(&d_cursor[dst[i]], 1);
        d_csr[o] = src[i];
    }
}

// ---------------- layer1 aggregation: half-warps x uint4 loads ----------------
// Warp per node. Lanes split into 2 halves (h = lane>>4); each half processes a
// different edge; lane covers 16B (8 dims) via LDG.128. Pairing across j/j+2.
__global__ void __launch_bounds__(256) k_agg1() {
    int gw = (blockIdx.x * blockDim.x + threadIdx.x) >> 5;
    int lane = threadIdx.x & 31;
    if (gw >= NODES) return;
    int s0 = d_row[gw], s1 = d_row[gw + 1];
    int h = lane >> 4, d = lane & 15;
    const uint4* x4 = (const uint4*)d_xh;
    float acc[8];
    #pragma unroll
    for (int i = 0; i < 8; i++) acc[i] = 0.f;
    for (int base = s0; base < s1; base += 32) {
        int rem = s1 - base;
        int sv = (lane < rem) ? d_csr[base + lane] : 0;
        int cnt = rem < 32 ? rem : 32;
        int j = 0;
        for (; j + 4 <= cnt; j += 4) {
            int ea = __shfl_sync(0xffffffffu, sv, j + h);
            int eb = __shfl_sync(0xffffffffu, sv, j + 2 + h);
            uint4 va = x4[(size_t)ea * 16 + d];
            uint4 vb = x4[(size_t)eb * 16 + d];
            uint32_t t0 = hadd2u(va.x, vb.x);
            uint32_t t1 = hadd2u(va.y, vb.y);
            uint32_t t2 = hadd2u(va.z, vb.z);
            uint32_t t3 = hadd2u(va.w, vb.w);
            float2 p0 = unph2(t0), p1 = unph2(t1), p2 = unph2(t2), p3 = unph2(t3);
            acc[0] += p0.x; acc[1] += p0.y; acc[2] += p1.x; acc[3] += p1.y;
            acc[4] += p2.x; acc[5] += p2.y; acc[6] += p3.x; acc[7] += p3.y;
        }
        for (; j < cnt; j += 2) {
            int e = j + h;
            int s = __shfl_sync(0xffffffffu, sv, e & 31);
            if (e < cnt) {
                uint4 v = x4[(size_t)s * 16 + d];
                float2 p0 = unph2(v.x), p1 = unph2(v.y), p2 = unph2(v.z), p3 = unph2(v.w);
                acc[0] += p0.x; acc[1] += p0.y; acc[2] += p1.x; acc[3] += p1.y;
                acc[4] += p2.x; acc[5] += p2.y; acc[6] += p3.x; acc[7] += p3.y;
            }
        }
    }
    #pragma unroll
    for (int i = 0; i < 8; i++) acc[i] += __shfl_xor_sync(0xffffffffu, acc[i], 16);
    int deg = s1 - s0;
    float sc = 1.0f / (float)(deg > 1 ? deg : 1);
    if (lane < 16) {
        uint4 o;
        o.x = packh2(acc[0] * sc, acc[1] * sc);
        o.y = packh2(acc[2] * sc, acc[3] * sc);
        o.z = packh2(acc[4] * sc, acc[5] * sc);
        o.w = packh2(acc[6] * sc, acc[7] * sc);
        ((uint4*)d_mean1h)[(size_t)gw * 16 + d] = o;
    }
}

// ---------------- fp16 tensor-core GEMMs (work-stealing tiles) ----------------
extern __shared__ uint32_t smu[];

// GEMM1: h1 = relu([mean1 | x] @ wt1 + b1), K=256 (8 chunks of 32)
__global__ void __launch_bounds__(256) k_gemm1(const float* __restrict__ b1) {
    uint32_t* Bp = smu;              // 16384 words (64 KB)
    uint32_t* Ab = smu + 16384;      // 2 * 2560 words (20 KB)
    __shared__ int s_tile;
    int tid = threadIdx.x, lane = tid & 31, w = tid >> 5;
    int wr = w >> 1, wc = w & 1;
    int g = lane >> 2, t = lane & 3;

    for (int i = tid; i < 4096; i += 256)
        ((uint4*)Bp)[i] = ((const uint4*)d_wt1p)[i];

    int arow = tid >> 1;
    int side = tid & 1;

    float bx[8], by[8];
    #pragma unroll
    for (int nf = 0; nf < 8; nf++) {
        int cc = wc * 64 + nf * 8 + 2 * t;
        bx[nf] = b1[cc]; by[nf] = b1[cc + 1];
    }

    for (;;) {
        if (tid == 0) s_tile = atomicAdd(&d_t1, 1);
        __syncthreads();                 // also covers initial Bp staging
        int tile = s_tile;
        if (tile >= TILES) break;
        int nb = tile << 7;
        float acc[2][8][4];
        #pragma unroll
        for (int mf = 0; mf < 2; mf++)
            #pragma unroll
            for (int nf = 0; nf < 8; nf++)
                #pragma unroll
                for (int q = 0; q < 4; q++) acc[mf][nf][q] = 0.f;

        uint4 rv[2];
        auto ldgch = [&](int c) {
            int node = nb + arow;
            const uint32_t* src;
            if (c < 4) src = (const uint32_t*)d_mean1h + (size_t)node * 64 + c * 16 + side * 8;
            else {
                int nc = node < NODES ? node : NODES - 1;
                src = (const uint32_t*)d_xh + (size_t)nc * 64 + (c - 4) * 16 + side * 8;
            }
            rv[0] = *(const uint4*)src;
            rv[1] = *(const uint4*)(src + 4);
        };
        auto stsch = [&](int buf) {
            uint32_t* p = Ab + buf * 2560 + arow * 20 + side * 8;
            *(uint4*)p = rv[0];
            *(uint4*)(p + 4) = rv[1];
        };

        ldgch(0);
        #pragma unroll 1
        for (int c = 0; c < 8; c++) {
            int buf = c & 1;
            stsch(buf);
            __syncthreads();
            if (c < 7) ldgch(c + 1);
            const uint32_t* ab0 = Ab + buf * 2560;
            #pragma unroll
            for (int ksub = 0; ksub < 2; ksub++) {
                uint32_t a[2][4];
                #pragma unroll
                for (int mf = 0; mf < 2; mf++) {
                    const uint32_t* base = ab0 + (wr * 32 + mf * 16 + g) * 20 + ksub * 8;
                    a[mf][0] = base[t];
                    a[mf][1] = base[160 + t];
                    a[mf][2] = base[t + 4];
                    a[mf][3] = base[160 + t + 4];
                }
                int ks16 = c * 2 + ksub;
                #pragma unroll
                for (int nf = 0; nf < 8; nf++) {
                    int n = wc * 64 + nf * 8 + g;
                    uint2 b = *(const uint2*)(Bp + ((ks16 * 128 + n) << 3) + (t << 1));
                    mmah(acc[0][nf], a[0], b);
                    mmah(acc[1][nf], a[1], b);
                }
            }
        }

        #pragma unroll
        for (int mf = 0; mf < 2; mf++) {
            int r0 = nb + wr * 32 + mf * 16 + g;
            #pragma unroll
            for (int nf = 0; nf < 8; nf++) {
                int cc = wc * 64 + nf * 8 + 2 * t;
                uint32_t v0 = packh2(fmaxf(acc[mf][nf][0] + bx[nf], 0.f),
                                     fmaxf(acc[mf][nf][1] + by[nf], 0.f));
                uint32_t v1 = packh2(fmaxf(acc[mf][nf][2] + bx[nf], 0.f),
                                     fmaxf(acc[mf][nf][3] + by[nf], 0.f));
                d_h1h[(size_t)r0 * 64 + (cc >> 1)] = v0;
                d_h1h[(size_t)(r0 + 8) * 64 + (cc >> 1)] = v1;
            }
        }
        __syncthreads();
    }
}

// GEMM2: [pl | pr] = h1 @ wt2, K=128 (4 chunks of 32)
__global__ void __launch_bounds__(256) k_gemm2() {
    uint32_t* Bp = smu;              // 8192 words (32 KB)
    uint32_t* Ab = smu + 8192;       // 2 * 2560 words (20 KB)
    __shared__ int s_tile;
    int tid = threadIdx.x, lane = tid & 31, w = tid >> 5;
    int wr = w >> 1, wc = w & 1;
    int g = lane >> 2, t = lane & 3;

    for (int i = tid; i < 2048; i += 256)
        ((uint4*)Bp)[i] = ((const uint4*)d_wt2p)[i];

    int arow = tid >> 1;
    int side = tid & 1;

    for (;;) {
        if (tid == 0) s_tile = atomicAdd(&d_t2, 1);
        __syncthreads();
        int tile = s_tile;
        if (tile >= TILES) break;
        int nb = tile << 7;
        float acc[2][8][4];
        #pragma unroll
        for (int mf = 0; mf < 2; mf++)
            #pragma unroll
            for (int nf = 0; nf < 8; nf++)
                #pragma unroll
                for (int q = 0; q < 4; q++) acc[mf][nf][q] = 0.f;

        uint4 rv[2];
        auto ldgch = [&](int c) {
            const uint32_t* src = d_h1h + (size_t)(nb + arow) * 64 + c * 16 + side * 8;
            rv[0] = *(const uint4*)src;
            rv[1] = *(const uint4*)(src + 4);
        };
        auto stsch = [&](int buf) {
            uint32_t* p = Ab + buf * 2560 + arow * 20 + side * 8;
            *(uint4*)p = rv[0];
            *(uint4*)(p + 4) = rv[1];
        };

        ldgch(0);
        #pragma unroll 1
        for (int c = 0; c < 4; c++) {
            int buf = c & 1;
            stsch(buf);
            __syncthreads();
            if (c < 3) ldgch(c + 1);
            const uint32_t* ab0 = Ab + buf * 2560;
            #pragma unroll
            for (int ksub = 0; ksub < 2; ksub++) {
                uint32_t a[2][4];
                #pragma unroll
                for (int mf = 0; mf < 2; mf++) {
                    const uint32_t* base = ab0 + (wr * 32 + mf * 16 + g) * 20 + ksub * 8;
                    a[mf][0] = base[t];
                    a[mf][1] = base[160 + t];
                    a[mf][2] = base[t + 4];
                    a[mf][3] = base[160 + t + 4];
                }
                int ks16 = c * 2 + ksub;
                #pragma unroll
                for (int nf = 0; nf < 8; nf++) {
                    int n = wc * 64 + nf * 8 + g;
                    uint2 b = *(const uint2*)(Bp + ((ks16 * 128 + n) << 3) + (t << 1));
                    mmah(acc[0][nf], a[0], b);
                    mmah(acc[1][nf], a[1], b);
                }
            }
        }

        #pragma unroll
        for (int mf = 0; mf < 2; mf++) {
            int r0 = nb + wr * 32 + mf * 16 + g;
            #pragma unroll
            for (int nf = 0; nf < 8; nf++) {
                int cc = wc * 64 + nf * 8 + 2 * t;
                uint32_t v0 = packh2(acc[mf][nf][0], acc[mf][nf][1]);
                uint32_t v1 = packh2(acc[mf][nf][2], acc[mf][nf][3]);
                if (wc == 0) {
                    d_plh[(size_t)r0 * 32 + (cc >> 1)] = v0;
                    d_plh[(size_t)(r0 + 8) * 32 + (cc >> 1)] = v1;
                } else {
                    d_prh[(size_t)r0 * 32 + ((cc - 64) >> 1)] = v0;
                    d_prh[(size_t)(r0 + 8) * 32 + ((cc - 64) >> 1)] = v1;
                }
            }
        }
        __syncthreads();
    }
}

// ---------------- layer2 agg + bias + relu + FC: quarter-warps x uint4 ----------------
// Warp per node. 4 quarter-warps (h = lane>>3) process 4 edges at once; lane
// covers 16B (8 dims) of the 128B pl row via LDG.128. Pairing across j/j+4.
__global__ void __launch_bounds__(256) k_agg2fc(const float* __restrict__ b2,
                                                const float* __restrict__ Wfc,
                                                const float* __restrict__ bfc,
                                                float* __restrict__ out) {
    int gw = (blockIdx.x * blockDim.x + threadIdx.x) >> 5;
    int lane = threadIdx.x & 31;
    if (gw >= NODES) return;
    int s0 = d_row[gw], s1 = d_row[gw + 1];
    int h = lane >> 3, d = lane & 7;
    const uint4* p4 = (const uint4*)d_plh;
    float acc[8];
    #pragma unroll
    for (int i = 0; i < 8; i++) acc[i] = 0.f;
    for (int base = s0; base < s1; base += 32) {
        int rem = s1 - base;
        int sv = (lane < rem) ? d_csr[base + lane] : 0;
        int cnt = rem < 32 ? rem : 32;
        int j = 0;
        for (; j + 8 <= cnt; j += 8) {
            int ea = __shfl_sync(0xffffffffu, sv, j + h);
            int eb = __shfl_sync(0xffffffffu, sv, j + 4 + h);
            uint4 va = p4[(size_t)ea * 8 + d];
            uint4 vb = p4[(size_t)eb * 8 + d];
            uint32_t t0 = hadd2u(va.x, vb.x);
            uint32_t t1 = hadd2u(va.y, vb.y);
            uint32_t t2 = hadd2u(va.z, vb.z);
            uint32_t t3 = hadd2u(va.w, vb.w);
            float2 p0 = unph2(t0), p1 = unph2(t1), p2 = unph2(t2), p3 = unph2(t3);
            acc[0] += p0.x; acc[1] += p0.y; acc[2] += p1.x; acc[3] += p1.y;
            acc[4] += p2.x; acc[5] += p2.y; acc[6] += p3.x; acc[7] += p3.y;
        }
        for (; j < cnt; j += 4) {
            int e = j + h;
            int s = __shfl_sync(0xffffffffu, sv, e & 31);
            if (e < cnt) {
                uint4 v = p4[(size_t)s * 8 + d];
                float2 p0 = unph2(v.x), p1 = unph2(v.y), p2 = unph2(v.z), p3 = unph2(v.w);
                acc[0] += p0.x; acc[1] += p0.y; acc[2] += p1.x; acc[3] += p1.y;
                acc[4] += p2.x; acc[5] += p2.y; acc[6] += p3.x; acc[7] += p3.y;
            }
        }
    }
    #pragma unroll
    for (int i = 0; i < 8; i++) {
        acc[i] += __shfl_xor_sync(0xffffffffu, acc[i], 8);
        acc[i] += __shfl_xor_sync(0xffffffffu, acc[i], 16);
    }
    int deg = s1 - s0;
    float sc = 1.0f / (float)(deg > 1 ? deg : 1);

    // epilogue: lane's 8 dims = 8d..8d+7 (all lanes compute; 4-way redundant)
    uint4 prv = ((const uint4*)d_prh)[(size_t)gw * 8 + d];
    float2 pr0 = unph2(prv.x), pr1 = unph2(prv.y), pr2 = unph2(prv.z), pr3 = unph2(prv.w);
    const float4* b2v = (const float4*)b2;
    float4 ba = b2v[2 * d], bb = b2v[2 * d + 1];
    const float4* wf = (const float4*)Wfc;
    float4 w0a = wf[2 * d], w0b = wf[2 * d + 1];
    float4 w1a = wf[16 + 2 * d], w1b = wf[16 + 2 * d + 1];

    float hv[8];
    hv[0] = fmaxf(acc[0] * sc + pr0.x + ba.x, 0.f);
    hv[1] = fmaxf(acc[1] * sc + pr0.y + ba.y, 0.f);
    hv[2] = fmaxf(acc[2] * sc + pr1.x + ba.z, 0.f);
    hv[3] = fmaxf(acc[3] * sc + pr1.y + ba.w, 0.f);
    hv[4] = fmaxf(acc[4] * sc + pr2.x + bb.x, 0.f);
    hv[5] = fmaxf(acc[5] * sc + pr2.y + bb.y, 0.f);
    hv[6] = fmaxf(acc[6] * sc + pr3.x + bb.z, 0.f);
    hv[7] = fmaxf(acc[7] * sc + pr3.y + bb.w, 0.f);

    float o0 = hv[0] * w0a.x + hv[1] * w0a.y + hv[2] * w0a.z + hv[3] * w0a.w
             + hv[4] * w0b.x + hv[5] * w0b.y + hv[6] * w0b.z + hv[7] * w0b.w;
    float o1 = hv[0] * w1a.x + hv[1] * w1a.y + hv[2] * w1a.z + hv[3] * w1a.w
             + hv[4] * w1b.x + hv[5] * w1b.y + hv[6] * w1b.z + hv[7] * w1b.w;
    #pragma unroll
    for (int o = 4; o; o >>= 1) {
        o0 += __shfl_xor_sync(0xffffffffu, o0, o);
        o1 += __shfl_xor_sync(0xffffffffu, o1, o);
    }
    if (lane == 0) {
        out[2 * gw]     = o0 + bfc[0];
        out[2 * gw + 1] = o1 + bfc[1];
    }
}

// ---------------- launch ----------------
extern "C" void kernel_launch(void* const* d_in, const int* in_sizes, int n_in,
                              void* d_out, int out_size) {
    const float* x   = (const float*)d_in[0];
    const int*   ei  = (const int*)d_in[1];
    const float* W1l = (const float*)d_in[2];
    const float* b1  = (const float*)d_in[3];
    const float* W1r = (const float*)d_in[4];
    const float* W2l = (const float*)d_in[5];
    const float* b2  = (const float*)d_in[6];
    const float* W2r = (const float*)d_in[7];
    const float* Wfc = (const float*)d_in[8];
    const float* bfc = (const float*)d_in[9];
    float* out = (float*)d_out;
    const int* src = ei;
    const int* dst = ei + EDGES;

    const int SMEM_G1 = (16384 + 2 * 2560) * 4;   // 86,016 B
    const int SMEM_G2 = (8192 + 2 * 2560) * 4;    // 53,248 B
    cudaFuncSetAttribute(k_gemm1, cudaFuncAttributeMaxDynamicSharedMemorySize, SMEM_G1);
    cudaFuncSetAttribute(k_gemm2, cudaFuncAttributeMaxDynamicSharedMemorySize, SMEM_G2);

    k_init<<<(NODES * 32 + 255) / 256, 256>>>(x, W1l, W1r, W2l, W2r);
    k_hist<<<(EDGES + 255) / 256, 256>>>(dst);
    k_scan<<<NCHUNK, CHUNK>>>();
    k_scatter<<<(EDGES + 255) / 256, 256>>>(src, dst);   // <- profiled slot (index 3)
    k_agg1<<<(NODES * 32 + 255) / 256, 256>>>();
    k_gemm1<<<296, 256, SMEM_G1>>>(b1);
    k_gemm2<<<592, 256, SMEM_G2>>>();
    k_agg2fc<<<(NODES * 32 + 255) / 256, 256>>>(b2, Wfc, bfc, out);
}

// round 15
// speedup vs baseline: 1.0841x; 1.0841x over previous
#include <cuda_runtime.h>
#include <cuda_fp16.h>
#include <cstdint>

#define NODES 100000
#define EDGES 1600000
#define TILES 782            // 782 * 128 = 100096
#define NPAD  100096
#define CHUNK 1024
#define NCHUNK 98

// ---------------- scratch (device globals; no allocation) ----------------
__device__ int   d_deg[NODES];          // zeroed by PREVIOUS launch's k_scan (or initial state)
__device__ int   d_cursor[NODES];       // initialized to row start by k_scan
__device__ int   d_row[NODES + 1];      // FINAL absolute CSR offsets
__device__ int   d_csr[EDGES];
__device__ int   d_tot[NCHUNK];
__device__ unsigned d_bar1;
__device__ int   d_t1, d_t2;            // GEMM tile work-stealing counters
__device__ uint2 d_xh[NODES * 32];      // x in fp16 (128 halfs/row)
__device__ uint2 d_mean1h[NPAD * 32];   // mean-aggregated x, fp16
__device__ uint32_t d_h1h[NPAD * 64];   // layer1 output, fp16
__device__ uint32_t d_plh[NPAD * 32];   // h1 @ W2l^T, fp16
__device__ uint32_t d_prh[NPAD * 32];   // h1 @ W2r^T, fp16
__device__ uint32_t d_wt1p[16384];      // [W1l;W1r] pre-packed fragment layout
__device__ uint32_t d_wt2p[8192];       // [W2l|W2r] pre-packed

// ---------------- helpers ----------------
__device__ __forceinline__ uint32_t packh2(float a, float b) {
    half2 h = __floats2half2_rn(a, b);
    return *(uint32_t*)&h;
}
__device__ __forceinline__ float2 unph2(uint32_t u) {
    return __half22float2(*(half2*)&u);
}
__device__ __forceinline__ uint32_t hadd2u(uint32_t a, uint32_t b) {
    half2 r = __hadd2(*(half2*)&a, *(half2*)&b);
    return *(uint32_t*)&r;
}

__device__ __forceinline__ void mmah(float* d, const uint32_t* a, uint2 b) {
    asm volatile(
        "mma.sync.aligned.m16n8k16.row.col.f32.f16.f16.f32 "
        "{%0,%1,%2,%3}, {%4,%5,%6,%7}, {%8,%9}, {%0,%1,%2,%3};\n"
        : "+f"(d[0]), "+f"(d[1]), "+f"(d[2]), "+f"(d[3])
        : "r"(a[0]), "r"(a[1]), "r"(a[2]), "r"(a[3]), "r"(b.x), "r"(b.y));
}

__device__ __forceinline__ float wt1_at(const float* W1l, const float* W1r, int n, int k) {
    return (k < 128) ? W1l[n * 128 + k] : W1r[n * 128 + (k - 128)];
}
__device__ __forceinline__ float wt2_at(const float* W2l, const float* W2r, int n, int k) {
    return (n < 64) ? W2l[n * 128 + k] : W2r[(n - 64) * 128 + k];
}

// ---------------- init: x->fp16 + weight pre-pack + FUSED histogram ----------------
// d_deg arrives zeroed (initial device state, then re-zeroed by k_scan each launch).
__global__ void k_init(const float* __restrict__ x,
                       const float* __restrict__ W1l, const float* __restrict__ W1r,
                       const float* __restrict__ W2l, const float* __restrict__ W2r,
                       const int* __restrict__ dst) {
    int i = blockIdx.x * blockDim.x + threadIdx.x;
    if (i == 0) { d_bar1 = 0; d_t1 = 0; d_t2 = 0; }
    if (i < NODES * 32) {
        float4 v = ((const float4*)x)[i];
        d_xh[i] = make_uint2(packh2(v.x, v.y), packh2(v.z, v.w));
    }
    if (i < EDGES) atomicAdd(&d_deg[dst[i]], 1);
    if (i < 16384) {
        int w = i & 7, n = (i >> 3) & 127, ks = i >> 10;
        int p = w >> 1;
        int kb = (w & 1) ? (2 * p + 8) : (2 * p);
        int k = ks * 16 + kb;
        d_wt1p[i] = packh2(wt1_at(W1l, W1r, n, k), wt1_at(W1l, W1r, n, k + 1));
    }
    if (i < 8192) {
        int w = i & 7, n = (i >> 3) & 127, ks = i >> 10;
        int p = w >> 1;
        int kb = (w & 1) ? (2 * p + 8) : (2 * p);
        int k = ks * 16 + kb;
        d_wt2p[i] = packh2(wt2_at(W2l, W2r, n, k), wt2_at(W2l, W2r, n, k + 1));
    }
}

// ---------------- merged scan (98 co-resident blocks, spin barrier) ----------------
// Consumes d_deg and RE-ZEROES it for the next launch (graph-replay invariant).
__global__ void __launch_bounds__(1024) k_scan() {
    __shared__ int ws[32];
    __shared__ int tot_s[128];
    __shared__ int s_off;
    int b = blockIdx.x;
    int i = b * CHUNK + threadIdx.x;
    int lane = threadIdx.x & 31, wid = threadIdx.x >> 5;

    int v = (i < NODES) ? d_deg[i] : 0;
    if (i < NODES) d_deg[i] = 0;        // reset for next launch
    int xv = v;
    #pragma unroll
    for (int o = 1; o < 32; o <<= 1) {
        int y = __shfl_up_sync(0xffffffffu, xv, o);
        if (lane >= o) xv += y;
    }
    if (lane == 31) ws[wid] = xv;
    __syncthreads();
    if (wid == 0) {
        int s = ws[lane];
        #pragma unroll
        for (int o = 1; o < 32; o <<= 1) {
            int y = __shfl_up_sync(0xffffffffu, s, o);
            if (lane >= o) s += y;
        }
        ws[lane] = s;
    }
    __syncthreads();
    int incl = xv + (wid > 0 ? ws[wid - 1] : 0);
    int excl = incl - v;
    if (threadIdx.x == CHUNK - 1) d_tot[b] = incl;

    __threadfence();
    __syncthreads();
    if (threadIdx.x == 0) {
        atomicAdd(&d_bar1, 1u);
        while (atomicAdd(&d_bar1, 0u) < (unsigned)gridDim.x) {}
    }
    __syncthreads();

    if (threadIdx.x < 128) tot_s[threadIdx.x] = (threadIdx.x < NCHUNK) ? d_tot[threadIdx.x] : 0;
    __syncthreads();
    if (threadIdx.x == 0) {
        int s = 0;
        for (int c = 0; c < b; c++) s += tot_s[c];
        s_off = s;
    }
    __syncthreads();
    int abs_off = excl + s_off;
    if (i <= NODES) d_row[i] = abs_off;
    if (i < NODES)  d_cursor[i] = abs_off;
}

// ---------------- scatter: 2 random accesses per edge ----------------
__global__ void k_scatter(const int* __restrict__ src, const int* __restrict__ dst) {
    int i = blockIdx.x * blockDim.x + threadIdx.x;
    if (i < EDGES) {
        int o = atomicAdd(&d_cursor[dst[i]], 1);
        d_csr[o] = src[i];
    }
}

// ---------------- layer1 aggregation: warp per node, 4-way fp16 tree ----------------
__global__ void __launch_bounds__(256) k_agg1() {
    int gw = (blockIdx.x * blockDim.x + threadIdx.x) >> 5;
    int lane = threadIdx.x & 31;
    if (gw >= NODES) return;
    int s0 = d_row[gw], s1 = d_row[gw + 1];
    float4 acc = make_float4(0.f, 0.f, 0.f, 0.f);
    for (int base = s0; base < s1; base += 32) {
        int rem = s1 - base;
        int sv = (lane < rem) ? d_csr[base + lane] : 0;
        int cnt = rem < 32 ? rem : 32;
        int j = 0;
        for (; j + 4 <= cnt; j += 4) {
            int sa = __shfl_sync(0xffffffffu, sv, j);
            int sb = __shfl_sync(0xffffffffu, sv, j + 1);
            int sc = __shfl_sync(0xffffffffu, sv, j + 2);
            int sd = __shfl_sync(0xffffffffu, sv, j + 3);
            uint2 va = d_xh[sa * 32 + lane];
            uint2 vb = d_xh[sb * 32 + lane];
            uint2 vc = d_xh[sc * 32 + lane];
            uint2 vd = d_xh[sd * 32 + lane];
            uint32_t t0 = hadd2u(hadd2u(va.x, vb.x), hadd2u(vc.x, vd.x));
            uint32_t t1 = hadd2u(hadd2u(va.y, vb.y), hadd2u(vc.y, vd.y));
            float2 p0 = unph2(t0), p1 = unph2(t1);
            acc.x += p0.x; acc.y += p0.y; acc.z += p1.x; acc.w += p1.y;
        }
        if (j + 2 <= cnt) {
            int sa = __shfl_sync(0xffffffffu, sv, j);
            int sb = __shfl_sync(0xffffffffu, sv, j + 1);
            uint2 va = d_xh[sa * 32 + lane];
            uint2 vb = d_xh[sb * 32 + lane];
            uint32_t t0 = hadd2u(va.x, vb.x);
            uint32_t t1 = hadd2u(va.y, vb.y);
            float2 p0 = unph2(t0), p1 = unph2(t1);
            acc.x += p0.x; acc.y += p0.y; acc.z += p1.x; acc.w += p1.y;
            j += 2;
        }
        if (j < cnt) {
            int s = __shfl_sync(0xffffffffu, sv, j);
            uint2 v = d_xh[s * 32 + lane];
            float2 p0 = unph2(v.x), p1 = unph2(v.y);
            acc.x += p0.x; acc.y += p0.y; acc.z += p1.x; acc.w += p1.y;
        }
    }
    int deg = s1 - s0;
    float sc = 1.0f / (float)(deg > 1 ? deg : 1);
    d_mean1h[gw * 32 + lane] =
        make_uint2(packh2(acc.x * sc, acc.y * sc), packh2(acc.z * sc, acc.w * sc));
}

// ---------------- fp16 tensor-core GEMMs (work-stealing tiles) ----------------
extern __shared__ uint32_t smu[];

// GEMM1: h1 = relu([mean1 | x] @ wt1 + b1), K=256 (8 chunks of 32)
__global__ void __launch_bounds__(256) k_gemm1(const float* __restrict__ b1) {
    uint32_t* Bp = smu;              // 16384 words (64 KB)
    uint32_t* Ab = smu + 16384;      // 2 * 2560 words (20 KB)
    __shared__ int s_tile;
    int tid = threadIdx.x, lane = tid & 31, w = tid >> 5;
    int wr = w >> 1, wc = w & 1;
    int g = lane >> 2, t = lane & 3;

    for (int i = tid; i < 4096; i += 256)
        ((uint4*)Bp)[i] = ((const uint4*)d_wt1p)[i];

    int arow = tid >> 1;
    int side = tid & 1;

    float bx[8], by[8];
    #pragma unroll
    for (int nf = 0; nf < 8; nf++) {
        int cc = wc * 64 + nf * 8 + 2 * t;
        bx[nf] = b1[cc]; by[nf] = b1[cc + 1];
    }

    for (;;) {
        if (tid == 0) s_tile = atomicAdd(&d_t1, 1);
        __syncthreads();                 // also covers initial Bp staging
        int tile = s_tile;
        if (tile >= TILES) break;
        int nb = tile << 7;
        float acc[2][8][4];
        #pragma unroll
        for (int mf = 0; mf < 2; mf++)
            #pragma unroll
            for (int nf = 0; nf < 8; nf++)
                #pragma unroll
                for (int q = 0; q < 4; q++) acc[mf][nf][q] = 0.f;

        uint4 rv[2];
        auto ldgch = [&](int c) {
            int node = nb + arow;
            const uint32_t* src;
            if (c < 4) src = (const uint32_t*)d_mean1h + (size_t)node * 64 + c * 16 + side * 8;
            else {
                int nc = node < NODES ? node : NODES - 1;
                src = (const uint32_t*)d_xh + (size_t)nc * 64 + (c - 4) * 16 + side * 8;
            }
            rv[0] = *(const uint4*)src;
            rv[1] = *(const uint4*)(src + 4);
        };
        auto stsch = [&](int buf) {
            uint32_t* p = Ab + buf * 2560 + arow * 20 + side * 8;
            *(uint4*)p = rv[0];
            *(uint4*)(p + 4) = rv[1];
        };

        ldgch(0);
        #pragma unroll 1
        for (int c = 0; c < 8; c++) {
            int buf = c & 1;
            stsch(buf);
            __syncthreads();
            if (c < 7) ldgch(c + 1);
            const uint32_t* ab0 = Ab + buf * 2560;
            #pragma unroll
            for (int ksub = 0; ksub < 2; ksub++) {
                uint32_t a[2][4];
                #pragma unroll
                for (int mf = 0; mf < 2; mf++) {
                    const uint32_t* base = ab0 + (wr * 32 + mf * 16 + g) * 20 + ksub * 8;
                    a[mf][0] = base[t];
                    a[mf][1] = base[160 + t];
                    a[mf][2] = base[t + 4];
                    a[mf][3] = base[160 + t + 4];
                }
                int ks16 = c * 2 + ksub;
                #pragma unroll
                for (int nf = 0; nf < 8; nf++) {
                    int n = wc * 64 + nf * 8 + g;
                    uint2 b = *(const uint2*)(Bp + ((ks16 * 128 + n) << 3) + (t << 1));
                    mmah(acc[0][nf], a[0], b);
                    mmah(acc[1][nf], a[1], b);
                }
            }
        }

        #pragma unroll
        for (int mf = 0; mf < 2; mf++) {
            int r0 = nb + wr * 32 + mf * 16 + g;
            #pragma unroll
            for (int nf = 0; nf < 8; nf++) {
                int cc = wc * 64 + nf * 8 + 2 * t;
                uint32_t v0 = packh2(fmaxf(acc[mf][nf][0] + bx[nf], 0.f),
                                     fmaxf(acc[mf][nf][1] + by[nf], 0.f));
                uint32_t v1 = packh2(fmaxf(acc[mf][nf][2] + bx[nf], 0.f),
                                     fmaxf(acc[mf][nf][3] + by[nf], 0.f));
                d_h1h[(size_t)r0 * 64 + (cc >> 1)] = v0;
                d_h1h[(size_t)(r0 + 8) * 64 + (cc >> 1)] = v1;
            }
        }
        __syncthreads();
    }
}

// GEMM2: [pl | pr] = h1 @ wt2, K=128 (4 chunks of 32)
__global__ void __launch_bounds__(256) k_gemm2() {
    uint32_t* Bp = smu;              // 8192 words (32 KB)
    uint32_t* Ab = smu + 8192;       // 2 * 2560 words (20 KB)
    __shared__ int s_tile;
    int tid = threadIdx.x, lane = tid & 31, w = tid >> 5;
    int wr = w >> 1, wc = w & 1;
    int g = lane >> 2, t = lane & 3;

    for (int i = tid; i < 2048; i += 256)
        ((uint4*)Bp)[i] = ((const uint4*)d_wt2p)[i];

    int arow = tid >> 1;
    int side = tid & 1;

    for (;;) {
        if (tid == 0) s_tile = atomicAdd(&d_t2, 1);
        __syncthreads();
        int tile = s_tile;
        if (tile >= TILES) break;
        int nb = tile << 7;
        float acc[2][8][4];
        #pragma unroll
        for (int mf = 0; mf < 2; mf++)
            #pragma unroll
            for (int nf = 0; nf < 8; nf++)
                #pragma unroll
                for (int q = 0; q < 4; q++) acc[mf][nf][q] = 0.f;

        uint4 rv[2];
        auto ldgch = [&](int c) {
            const uint32_t* src = d_h1h + (size_t)(nb + arow) * 64 + c * 16 + side * 8;
            rv[0] = *(const uint4*)src;
            rv[1] = *(const uint4*)(src + 4);
        };
        auto stsch = [&](int buf) {
            uint32_t* p = Ab + buf * 2560 + arow * 20 + side * 8;
            *(uint4*)p = rv[0];
            *(uint4*)(p + 4) = rv[1];
        };

        ldgch(0);
        #pragma unroll 1
        for (int c = 0; c < 4; c++) {
            int buf = c & 1;
            stsch(buf);
            __syncthreads();
            if (c < 3) ldgch(c + 1);
            const uint32_t* ab0 = Ab + buf * 2560;
            #pragma unroll
            for (int ksub = 0; ksub < 2; ksub++) {
                uint32_t a[2][4];
                #pragma unroll
                for (int mf = 0; mf < 2; mf++) {
                    const uint32_t* base = ab0 + (wr * 32 + mf * 16 + g) * 20 + ksub * 8;
                    a[mf][0] = base[t];
                    a[mf][1] = base[160 + t];
                    a[mf][2] = base[t + 4];
                    a[mf][3] = base[160 + t + 4];
                }
                int ks16 = c * 2 + ksub;
                #pragma unroll
                for (int nf = 0; nf < 8; nf++) {
                    int n = wc * 64 + nf * 8 + g;
                    uint2 b = *(const uint2*)(Bp + ((ks16 * 128 + n) << 3) + (t << 1));
                    mmah(acc[0][nf], a[0], b);
                    mmah(acc[1][nf], a[1], b);
                }
            }
        }

        #pragma unroll
        for (int mf = 0; mf < 2; mf++) {
            int r0 = nb + wr * 32 + mf * 16 + g;
            #pragma unroll
            for (int nf = 0; nf < 8; nf++) {
                int cc = wc * 64 + nf * 8 + 2 * t;
                uint32_t v0 = packh2(acc[mf][nf][0], acc[mf][nf][1]);
                uint32_t v1 = packh2(acc[mf][nf][2], acc[mf][nf][3]);
                if (wc == 0) {
                    d_plh[(size_t)r0 * 32 + (cc >> 1)] = v0;
                    d_plh[(size_t)(r0 + 8) * 32 + (cc >> 1)] = v1;
                } else {
                    d_prh[(size_t)r0 * 32 + ((cc - 64) >> 1)] = v0;
                    d_prh[(size_t)(r0 + 8) * 32 + ((cc - 64) >> 1)] = v1;
                }
            }
        }
        __syncthreads();
    }
}

// ---------------- layer2 aggregation + bias + relu + FC, fused (4-way) ----------------
__global__ void __launch_bounds__(256) k_agg2fc(const float* __restrict__ b2,
                                                const float* __restrict__ Wfc,
                                                const float* __restrict__ bfc,
                                                float* __restrict__ out) {
    int gw = (blockIdx.x * blockDim.x + threadIdx.x) >> 5;
    int lane = threadIdx.x & 31;
    if (gw >= NODES) return;
    int s0 = d_row[gw], s1 = d_row[gw + 1];
    float a0 = 0.f, a1 = 0.f;
    for (int base = s0; base < s1; base += 32) {
        int rem = s1 - base;
        int sv = (lane < rem) ? d_csr[base + lane] : 0;
        int cnt = rem < 32 ? rem : 32;
        int j = 0;
        for (; j + 4 <= cnt; j += 4) {
            int sa = __shfl_sync(0xffffffffu, sv, j);
            int sb = __shfl_sync(0xffffffffu, sv, j + 1);
            int sc = __shfl_sync(0xffffffffu, sv, j + 2);
            int sd = __shfl_sync(0xffffffffu, sv, j + 3);
            uint32_t t0 = hadd2u(hadd2u(d_plh[sa * 32 + lane], d_plh[sb * 32 + lane]),
                                 hadd2u(d_plh[sc * 32 + lane], d_plh[sd * 32 + lane]));
            float2 p = unph2(t0);
            a0 += p.x; a1 += p.y;
        }
        if (j + 2 <= cnt) {
            int sa = __shfl_sync(0xffffffffu, sv, j);
            int sb = __shfl_sync(0xffffffffu, sv, j + 1);
            uint32_t t0 = hadd2u(d_plh[sa * 32 + lane], d_plh[sb * 32 + lane]);
            float2 p = unph2(t0);
            a0 += p.x; a1 += p.y;
            j += 2;
        }
        if (j < cnt) {
            int s = __shfl_sync(0xffffffffu, sv, j);
            float2 v = unph2(d_plh[s * 32 + lane]);
            a0 += v.x; a1 += v.y;
        }
    }
    int deg = s1 - s0;
    float sc = 1.0f / (float)(deg > 1 ? deg : 1);
    float2 pr = unph2(d_prh[gw * 32 + lane]);
    float2 bb = ((const float2*)b2)[lane];
    float h0 = fmaxf(a0 * sc + pr.x + bb.x, 0.f);
    float h1 = fmaxf(a1 * sc + pr.y + bb.y, 0.f);
    float2 w0 = ((const float2*)Wfc)[lane];
    float2 w1 = ((const float2*)Wfc)[32 + lane];
    float o0 = h0 * w0.x + h1 * w0.y;
    float o1 = h0 * w1.x + h1 * w1.y;
    #pragma unroll
    for (int o = 16; o; o >>= 1) {
        o0 += __shfl_xor_sync(0xffffffffu, o0, o);
        o1 += __shfl_xor_sync(0xffffffffu, o1, o);
    }
    if (lane == 0) {
        out[2 * gw]     = o0 + bfc[0];
        out[2 * gw + 1] = o1 + bfc[1];
    }
}

// ---------------- launch ----------------
extern "C" void kernel_launch(void* const* d_in, const int* in_sizes, int n_in,
                              void* d_out, int out_size) {
    const float* x   = (const float*)d_in[0];
    const int*   ei  = (const int*)d_in[1];
    const float* W1l = (const float*)d_in[2];
    const float* b1  = (const float*)d_in[3];
    const float* W1r = (const float*)d_in[4];
    const float* W2l = (const float*)d_in[5];
    const float* b2  = (const float*)d_in[6];
    const float* W2r = (const float*)d_in[7];
    const float* Wfc = (const float*)d_in[8];
    const float* bfc = (const float*)d_in[9];
    float* out = (float*)d_out;
    const int* src = ei;
    const int* dst = ei + EDGES;

    const int SMEM_G1 = (16384 + 2 * 2560) * 4;   // 86,016 B
    const int SMEM_G2 = (8192 + 2 * 2560) * 4;    // 53,248 B
    cudaFuncSetAttribute(k_gemm1, cudaFuncAttributeMaxDynamicSharedMemorySize, SMEM_G1);
    cudaFuncSetAttribute(k_gemm2, cudaFuncAttributeMaxDynamicSharedMemorySize, SMEM_G2);

    k_init<<<(NODES * 32 + 255) / 256, 256>>>(x, W1l, W1r, W2l, W2r, dst);
    k_scan<<<NCHUNK, CHUNK>>>();
    k_scatter<<<(EDGES + 255) / 256, 256>>>(src, dst);
    k_agg1<<<(NODES * 32 + 255) / 256, 256>>>();         // <- profiled slot (index 3)
    k_gemm1<<<296, 256, SMEM_G1>>>(b1);
    k_gemm2<<<592, 256, SMEM_G2>>>();
    k_agg2fc<<<(NODES * 32 + 255) / 256, 256>>>(b2, Wfc, bfc, out);
}